// round 12
// baseline (speedup 1.0000x reference)
#include <cuda_runtime.h>
#include <cuda_fp16.h>
#include <stdint.h>
#include <math.h>

#define NN 100000
#define EE 1600000
#define D  128

// ---------------- device scratch (no allocations allowed) -------------------
__device__ __align__(16) __half g_f16[(size_t)NN * D];   // layer-0 input (x fp16)
__device__ __align__(16) __half g_h16[(size_t)NN * D];   // layer-0 output (h1 fp16)
__device__ __align__(16) __half g_w16a[128 * 256];       // [Wl0;Wr0] fp16 [n][k]
__device__ __align__(16) __half g_w16b[128 * 256];       // [Wl1;Wr1] fp16 [n][k]
// zeroed-each-call region: cnt[NN], flag[128], agg[128], inc[128], ticket
__device__ int g_zero[NN + 385];
#define ZF_FLAG  (NN)
#define ZF_AGG   (NN + 128)
#define ZF_INC   (NN + 256)
#define ZF_TKT   (NN + 384)
__device__ int g_off[NN + 1];
__device__ int g_cur[NN];
__device__ int g_csr[EE];
__device__ float g_s[NN];
__device__ float g_z[NN];

// ---------------- K1: convert_x + edge count (int4) + weight prep -----------
__global__ void prep_all(const float* __restrict__ x,
                         const int* __restrict__ dst,
                         const float* __restrict__ Wl0, const float* __restrict__ Wr0,
                         const float* __restrict__ Wl1, const float* __restrict__ Wr1,
                         int n, int E) {
    int gsz = gridDim.x * blockDim.x;
    int i0 = blockIdx.x * blockDim.x + threadIdx.x;

    int n4 = n * 32;
    for (int i = i0; i < n4; i += gsz) {
        float4 v = __ldg(((const float4*)x) + i);
        __half2 a = __floats2half2_rn(v.x, v.y);
        __half2 b = __floats2half2_rn(v.z, v.w);
        uint2 F;
        F.x = *(unsigned*)&a;
        F.y = *(unsigned*)&b;
        *((uint2*)(g_f16 + (size_t)i * 4)) = F;
    }
    int E4 = E >> 2;
    for (int i = i0; i < E4; i += gsz) {
        int4 d4 = __ldg(((const int4*)dst) + i);
        atomicAdd(&g_zero[d4.x], 1);
        atomicAdd(&g_zero[d4.y], 1);
        atomicAdd(&g_zero[d4.z], 1);
        atomicAdd(&g_zero[d4.w], 1);
    }
    for (int i = E4 * 4 + i0; i < E; i += gsz)
        atomicAdd(&g_zero[__ldg(dst + i)], 1);
    for (int i = i0; i < 32768; i += gsz) {
        int nrow = i >> 8, k = i & 255;
        int widx = nrow * 128 + (k & 127);
        float w0 = (k < 128) ? __ldg(Wl0 + widx) : __ldg(Wr0 + widx);
        float w1 = (k < 128) ? __ldg(Wl1 + widx) : __ldg(Wr1 + widx);
        g_w16a[nrow * 256 + k] = __float2half_rn(w0);
        g_w16b[nrow * 256 + k] = __float2half_rn(w1);
    }
}

// ---------------- K2: single-pass scan (decoupled lookback) -----------------
__global__ void scan_lb(int n, int E) {
    __shared__ int s[1024];
    __shared__ int sbid, sprev;
    int tid = threadIdx.x;
    if (tid == 0) sbid = atomicAdd(&g_zero[ZF_TKT], 1);
    __syncthreads();
    int bid = sbid;
    int i = bid * 1024 + tid;
    int v = (i < n) ? g_zero[i] : 0;
    s[tid] = v;
    __syncthreads();
    for (int off = 1; off < 1024; off <<= 1) {
        int t = (tid >= off) ? s[tid - off] : 0;
        __syncthreads();
        s[tid] += t;
        __syncthreads();
    }
    if (tid == 0) {
        int total = s[1023];
        if (bid == 0) {
            atomicExch(&g_zero[ZF_INC + 0], total);
            __threadfence();
            atomicExch(&g_zero[ZF_FLAG + 0], 2);
            sprev = 0;
        } else {
            atomicExch(&g_zero[ZF_AGG + bid], total);
            __threadfence();
            atomicExch(&g_zero[ZF_FLAG + bid], 1);
            int prev = 0, j = bid - 1;
            while (1) {
                int f;
                do { f = atomicAdd(&g_zero[ZF_FLAG + j], 0); } while (f == 0);
                if (f == 2) { prev += atomicAdd(&g_zero[ZF_INC + j], 0); break; }
                prev += atomicAdd(&g_zero[ZF_AGG + j], 0);
                --j;
            }
            atomicExch(&g_zero[ZF_INC + bid], prev + total);
            __threadfence();
            atomicExch(&g_zero[ZF_FLAG + bid], 2);
            sprev = prev;
        }
    }
    __syncthreads();
    int off = sprev + s[tid] - v;   // exclusive prefix
    if (i < n) { g_off[i] = off; g_cur[i] = off; }
    if (i == n) g_off[n] = E;
}

// ---------------- K3: CSR fill (int4 edge loads) -----------------------------
__global__ void fill_kernel(const int* __restrict__ src,
                            const int* __restrict__ dst, int E) {
    int i = blockIdx.x * blockDim.x + threadIdx.x;
    int stride = gridDim.x * blockDim.x;
    int E4 = E >> 2;
    for (int j = i; j < E4; j += stride) {
        int4 s4 = __ldg(((const int4*)src) + j);
        int4 d4 = __ldg(((const int4*)dst) + j);
        g_csr[atomicAdd(&g_cur[d4.x], 1)] = s4.x;
        g_csr[atomicAdd(&g_cur[d4.y], 1)] = s4.y;
        g_csr[atomicAdd(&g_cur[d4.z], 1)] = s4.z;
        g_csr[atomicAdd(&g_cur[d4.w], 1)] = s4.w;
    }
    for (int j = E4 * 4 + i; j < E; j += stride) {
        int pos = atomicAdd(&g_cur[dst[j]], 1);
        g_csr[pos] = src[j];
    }
}

// =============================================================================
// Fused gather + fp16 mma.sync GEMM (persistent, 148 CTAs, 512 threads):
//   per 256-row tile: gather mean(neighbors of feat) into smem A agg half,
//   feat half via cp.async (16 segs x 16B = 256B/row), then K=256 mma.
// feat (input) and outF16 (output) are DIFFERENT buffers (gather reads
// arbitrary neighbor rows while other blocks write their tiles).
// =============================================================================
#define GEMM_GRID 148
#define TM 256
#define SM_B    0        // W fp16 [128][264] (67584 B)
#define SM_A    67584    // A fp16 [256][264] (135168 B); row = [agg|feat]
#define SM_RED  202752   // sS[256], sZ[256], sWl2[128], sWr2[128], sB[128]
#define GEMM_SMEM 206336

__device__ __forceinline__ unsigned su32(const void* p) {
    return (unsigned)__cvta_generic_to_shared(p);
}
__device__ __forceinline__ void cpa16(unsigned dst, const void* src, bool ok) {
    asm volatile("cp.async.cg.shared.global [%0], [%1], 16, %2;"
                 :: "r"(dst), "l"(src), "r"(ok ? 16 : 0));
}
__device__ __forceinline__ void ldm4(unsigned* r, unsigned addr) {
    asm volatile("ldmatrix.sync.aligned.m8n8.x4.shared.b16 {%0,%1,%2,%3}, [%4];"
                 : "=r"(r[0]), "=r"(r[1]), "=r"(r[2]), "=r"(r[3]) : "r"(addr));
}
__device__ __forceinline__ void mma16(float* d, const unsigned* a,
                                      unsigned b0, unsigned b1) {
    asm volatile(
        "mma.sync.aligned.m16n8k16.row.col.f32.f16.f16.f32 "
        "{%0,%1,%2,%3}, {%4,%5,%6,%7}, {%8,%9}, {%0,%1,%2,%3};"
        : "+f"(d[0]), "+f"(d[1]), "+f"(d[2]), "+f"(d[3])
        : "r"(a[0]), "r"(a[1]), "r"(a[2]), "r"(a[3]), "r"(b0), "r"(b1));
}
__device__ __forceinline__ void acc2(float4& acc, uint2 r0, uint2 r1) {
    __half2 p0 = __hadd2(*(__half2*)&r0.x, *(__half2*)&r1.x);
    __half2 p1 = __hadd2(*(__half2*)&r0.y, *(__half2*)&r1.y);
    float2 f0 = __half22float2(p0);
    float2 f1 = __half22float2(p1);
    acc.x += f0.x; acc.y += f0.y; acc.z += f1.x; acc.w += f1.y;
}

__global__ __launch_bounds__(512, 1) void gemm_fused(
    const __half* __restrict__ feat,
    const __half* __restrict__ w16,
    const float* __restrict__ bias,
    __half* __restrict__ outF16,
    const float* __restrict__ Wl2, const float* __restrict__ Wr2,
    int n, int mode)
{
    extern __shared__ char sm[];
    unsigned smb = su32(sm);
    float* sS   = (float*)(sm + SM_RED);   // [256]
    float* sZ   = sS + 256;                // [256]
    float* sWl2 = sZ + 256;                // [128]
    float* sWr2 = sWl2 + 128;              // [128]
    float* sB   = sWr2 + 128;              // [128]

    int tid = threadIdx.x;
    int lane = tid & 31;
    int wid = tid >> 5;
    int mwarp = wid & 7;          // rows [mwarp*32, +32)
    int nwarp = wid >> 3;         // cols [nwarp*64, +64)
    int ntiles = (n + TM - 1) / TM;

    if (tid < 128) {
        sB[tid] = bias[tid];
        if (mode == 1) { sWl2[tid] = Wl2[tid]; sWr2[tid] = Wr2[tid]; }
    }
    // W resident load
    #pragma unroll
    for (int u = tid; u < 4096; u += 512) {
        int nrow = u >> 5, kc = u & 31;
        cpa16(smb + SM_B + nrow * 528 + kc * 16, w16 + nrow * 256 + kc * 8, true);
    }
    asm volatile("cp.async.commit_group;");

    // ldmatrix per-thread addresses
    unsigned aAddr = smb + SM_A
        + (mwarp * 32 + (lane & 7) + ((lane >> 3) & 1) * 8) * 528
        + ((lane >> 4) & 1) * 16;
    unsigned bAddr = smb + SM_B
        + (nwarp * 64 + (lane & 7) + ((lane >> 4) & 1) * 8) * 528
        + ((lane >> 3) & 1) * 16;

    int g = lane >> 2, tq = lane & 3;
    const uint2* hb = ((const uint2*)feat) + lane;   // row r -> hb[r*32]

    for (int t = blockIdx.x; t < ntiles; t += gridDim.x) {
        if (mode == 1 && tid < 256) { sS[tid] = 0.f; sZ[tid] = 0.f; }

        // feat half of A via cp.async: 16 segs x 16B = 256B per row
        #pragma unroll
        for (int u = tid; u < 4096; u += 512) {
            int r = u >> 4, seg = u & 15;
            int row = t * TM + r;
            bool ok = row < n;
            cpa16(smb + SM_A + r * 528 + 256 + seg * 16,
                  feat + (size_t)(ok ? row : 0) * 128 + seg * 8, ok);
        }
        asm volatile("cp.async.commit_group;");

        // gather agg half of A: warp per row, 16 rows per warp
        for (int rr = wid; rr < TM; rr += 16) {
            int row = t * TM + rr;
            if (row < n) {
                int beg = g_off[row], end = g_off[row + 1];
                float4 acc = make_float4(0.f, 0.f, 0.f, 0.f);
                int e = beg;
                for (; e + 7 < end; e += 8) {
                    int s0 = __ldg(g_csr + e),     s1 = __ldg(g_csr + e + 1);
                    int s2 = __ldg(g_csr + e + 2), s3 = __ldg(g_csr + e + 3);
                    int s4 = __ldg(g_csr + e + 4), s5 = __ldg(g_csr + e + 5);
                    int s6 = __ldg(g_csr + e + 6), s7 = __ldg(g_csr + e + 7);
                    uint2 r0 = __ldg(hb + s0 * 32), r1 = __ldg(hb + s1 * 32);
                    uint2 r2 = __ldg(hb + s2 * 32), r3 = __ldg(hb + s3 * 32);
                    uint2 r4 = __ldg(hb + s4 * 32), r5 = __ldg(hb + s5 * 32);
                    uint2 r6 = __ldg(hb + s6 * 32), r7 = __ldg(hb + s7 * 32);
                    acc2(acc, r0, r1);
                    acc2(acc, r2, r3);
                    acc2(acc, r4, r5);
                    acc2(acc, r6, r7);
                }
                for (; e + 1 < end; e += 2) {
                    int s0 = __ldg(g_csr + e), s1 = __ldg(g_csr + e + 1);
                    uint2 r0 = __ldg(hb + s0 * 32), r1 = __ldg(hb + s1 * 32);
                    acc2(acc, r0, r1);
                }
                if (e < end) {
                    int s = __ldg(g_csr + e);
                    uint2 raw = __ldg(hb + s * 32);
                    float2 f01 = __half22float2(*(__half2*)&raw.x);
                    float2 f23 = __half22float2(*(__half2*)&raw.y);
                    acc.x += f01.x; acc.y += f01.y; acc.z += f23.x; acc.w += f23.y;
                }
                float inv = 1.0f / fmaxf((float)(end - beg), 1.0f);
                __half2 h01 = __floats2half2_rn(acc.x * inv, acc.y * inv);
                __half2 h23 = __floats2half2_rn(acc.z * inv, acc.w * inv);
                uint2 o;
                o.x = *(unsigned*)&h01;
                o.y = *(unsigned*)&h23;
                *((uint2*)(sm + SM_A + rr * 528 + lane * 8)) = o;
            }
        }

        asm volatile("cp.async.wait_group 0;");
        __syncthreads();

        float acc[2][8][4];
        #pragma unroll
        for (int h = 0; h < 2; ++h)
            #pragma unroll
            for (int i = 0; i < 8; ++i)
                #pragma unroll
                for (int j = 0; j < 4; ++j) acc[h][i][j] = 0.f;

        #pragma unroll
        for (int k = 0; k < 16; ++k) {
            unsigned a0[4], a1[4], b[4];
            ldm4(a0, aAddr + k * 32);
            ldm4(a1, aAddr + 16 * 528 + k * 32);
            #pragma unroll
            for (int p = 0; p < 4; ++p) {
                ldm4(b, bAddr + p * 16 * 528 + k * 32);
                mma16(acc[0][2 * p],     a0, b[0], b[1]);
                mma16(acc[0][2 * p + 1], a0, b[2], b[3]);
                mma16(acc[1][2 * p],     a1, b[0], b[1]);
                mma16(acc[1][2 * p + 1], a1, b[2], b[3]);
            }
        }
        __syncthreads();           // all warps done with A smem

        // ---- epilogue ----
        #pragma unroll
        for (int h = 0; h < 2; ++h) {
            int r0 = t * TM + mwarp * 32 + h * 16 + g;
            int r1 = r0 + 8;
            float ps0 = 0.f, pz0 = 0.f, ps1 = 0.f, pz1 = 0.f;
            #pragma unroll
            for (int nt = 0; nt < 8; ++nt) {
                int col = nwarp * 64 + nt * 8 + tq * 2;
                float b0 = sB[col], b1 = sB[col + 1];
                float v0 = fmaxf(acc[h][nt][0] + b0, 0.f);
                float v1 = fmaxf(acc[h][nt][1] + b1, 0.f);
                float v2 = fmaxf(acc[h][nt][2] + b0, 0.f);
                float v3 = fmaxf(acc[h][nt][3] + b1, 0.f);
                if (mode == 0) {
                    if (r0 < n) {
                        __half2 f = __floats2half2_rn(v0, v1);
                        *((unsigned*)(outF16 + (size_t)r0 * D + col)) = *(unsigned*)&f;
                    }
                    if (r1 < n) {
                        __half2 f = __floats2half2_rn(v2, v3);
                        *((unsigned*)(outF16 + (size_t)r1 * D + col)) = *(unsigned*)&f;
                    }
                } else {
                    float wl0 = sWl2[col], wl1 = sWl2[col + 1];
                    float wr0 = sWr2[col], wr1 = sWr2[col + 1];
                    ps0 += v0 * wl0 + v1 * wl1;
                    pz0 += v0 * wr0 + v1 * wr1;
                    ps1 += v2 * wl0 + v3 * wl1;
                    pz1 += v2 * wr0 + v3 * wr1;
                }
            }
            if (mode == 1) {
                #pragma unroll
                for (int m = 1; m <= 2; m <<= 1) {
                    ps0 += __shfl_xor_sync(0xffffffffu, ps0, m);
                    pz0 += __shfl_xor_sync(0xffffffffu, pz0, m);
                    ps1 += __shfl_xor_sync(0xffffffffu, ps1, m);
                    pz1 += __shfl_xor_sync(0xffffffffu, pz1, m);
                }
                if (tq == 0) {
                    int lr = mwarp * 32 + h * 16 + g;
                    atomicAdd(&sS[lr], ps0);
                    atomicAdd(&sZ[lr], pz0);
                    atomicAdd(&sS[lr + 8], ps1);
                    atomicAdd(&sZ[lr + 8], pz1);
                }
            }
        }
        if (mode == 1) {
            __syncthreads();
            if (tid < 256) {
                int row = t * TM + tid;
                if (row < n) { g_s[row] = sS[tid]; g_z[row] = sZ[tid]; }
            }
        }
    }
}

// ---------------- final: mean-gather scalar + bias + sigmoid ----------------
__global__ void final_fused(const float* __restrict__ bl2,
                            float* __restrict__ out, int n) {
    int i = blockIdx.x * blockDim.x + threadIdx.x;
    if (i >= n) return;
    int beg = g_off[i], end = g_off[i + 1];
    float acc = 0.f;
    int e = beg;
    for (; e + 3 < end; e += 4) {
        float a0 = g_s[__ldg(g_csr + e)];
        float a1 = g_s[__ldg(g_csr + e + 1)];
        float a2 = g_s[__ldg(g_csr + e + 2)];
        float a3 = g_s[__ldg(g_csr + e + 3)];
        acc += (a0 + a1) + (a2 + a3);
    }
    for (; e < end; ++e) acc += g_s[__ldg(g_csr + e)];
    float v = acc / fmaxf((float)(end - beg), 1.0f) + __ldg(bl2) + g_z[i];
    out[i] = v;
    out[n + i] = 1.0f / (1.0f + expf(-v));
}

// ---------------------------------------------------------------------------
extern "C" void kernel_launch(void* const* d_in, const int* in_sizes, int n_in,
                              void* d_out, int out_size) {
    const float* x   = (const float*)d_in[0];
    const int*   ei  = (const int*)d_in[1];
    const float* Wl0 = (const float*)d_in[2];
    const float* bl0 = (const float*)d_in[3];
    const float* Wr0 = (const float*)d_in[4];
    const float* Wl1 = (const float*)d_in[5];
    const float* bl1 = (const float*)d_in[6];
    const float* Wr1 = (const float*)d_in[7];
    const float* Wl2 = (const float*)d_in[8];
    const float* bl2 = (const float*)d_in[9];
    const float* Wr2 = (const float*)d_in[10];
    float* out = (float*)d_out;

    int n = in_sizes[0] / D;   // 100000
    int E = in_sizes[1] / 2;   // 1600000
    const int* src = ei;
    const int* dst = ei + E;

    void* p_zero;
    cudaGetSymbolAddress(&p_zero, g_zero);
    __half *f16, *h16, *w16a, *w16b;
    cudaGetSymbolAddress((void**)&f16, g_f16);
    cudaGetSymbolAddress((void**)&h16, g_h16);
    cudaGetSymbolAddress((void**)&w16a, g_w16a);
    cudaGetSymbolAddress((void**)&w16b, g_w16b);

    cudaFuncSetAttribute(gemm_fused, cudaFuncAttributeMaxDynamicSharedMemorySize,
                         GEMM_SMEM);

    int scan_blocks = (n + 1024) / 1024;  // 98 (covers i==n too)
    int fill_blocks = ((E >> 2) + 255) / 256;  // 1563

    cudaMemsetAsync(p_zero, 0, (size_t)(NN + 385) * sizeof(int));
    prep_all<<<12500, 256>>>(x, dst, Wl0, Wr0, Wl1, Wr1, n, E);
    scan_lb<<<scan_blocks, 1024>>>(n, E);
    fill_kernel<<<fill_blocks, 256>>>(src, dst, E);

    // Layer 0: fused gather + gemm; reads f16 (x), writes h16 (h1) — no alias
    gemm_fused<<<GEMM_GRID, 512, GEMM_SMEM>>>(f16, w16a, bl0, h16,
                                              (const float*)0, (const float*)0,
                                              n, 0);
    // Layer 1 + layer-2 scalarization: reads h16, writes g_s/g_z
    gemm_fused<<<GEMM_GRID, 512, GEMM_SMEM>>>(h16, w16b, bl1, (__half*)0,
                                              Wl2, Wr2, n, 1);
    // Layer 2 aggregation + output
    final_fused<<<(n + 255) / 256, 256>>>(bl2, out, n);
}

// round 13
// speedup vs baseline: 1.4580x; 1.4580x over previous
#include <cuda_runtime.h>
#include <cuda_fp16.h>
#include <stdint.h>
#include <math.h>

#define NN 100000
#define EE 1600000
#define D  128

// ---------------- device scratch (no allocations allowed) -------------------
__device__ __align__(16) __half g_a16[(size_t)NN * D];   // agg fp16
__device__ __align__(16) __half g_f16[(size_t)NN * D];   // feat fp16 (x -> h1)
__device__ __align__(16) __half g_w16a[128 * 256];       // [Wl0;Wr0] fp16 [n][k]
__device__ __align__(16) __half g_w16b[128 * 256];       // [Wl1;Wr1] fp16 [n][k]
// zeroed-each-call region: cnt[NN], flag[128], agg[128], inc[128], ticket
__device__ int g_zero[NN + 385];
#define ZF_FLAG  (NN)
#define ZF_AGG   (NN + 128)
#define ZF_INC   (NN + 256)
#define ZF_TKT   (NN + 384)
__device__ int g_off[NN + 1];
__device__ int g_cur[NN];
__device__ int g_csr[EE];
__device__ float g_s[NN];
__device__ float g_z[NN];

// ---------------- K1: convert_x + edge count (int4) + weight prep -----------
__global__ void prep_all(const float* __restrict__ x,
                         const int* __restrict__ dst,
                         const float* __restrict__ Wl0, const float* __restrict__ Wr0,
                         const float* __restrict__ Wl1, const float* __restrict__ Wr1,
                         int n, int E) {
    int gsz = gridDim.x * blockDim.x;
    int i0 = blockIdx.x * blockDim.x + threadIdx.x;

    int n4 = n * 32;
    for (int i = i0; i < n4; i += gsz) {
        float4 v = __ldg(((const float4*)x) + i);
        __half2 a = __floats2half2_rn(v.x, v.y);
        __half2 b = __floats2half2_rn(v.z, v.w);
        uint2 F;
        F.x = *(unsigned*)&a;
        F.y = *(unsigned*)&b;
        *((uint2*)(g_f16 + (size_t)i * 4)) = F;
    }
    int E4 = E >> 2;
    for (int i = i0; i < E4; i += gsz) {
        int4 d4 = __ldg(((const int4*)dst) + i);
        atomicAdd(&g_zero[d4.x], 1);
        atomicAdd(&g_zero[d4.y], 1);
        atomicAdd(&g_zero[d4.z], 1);
        atomicAdd(&g_zero[d4.w], 1);
    }
    for (int i = E4 * 4 + i0; i < E; i += gsz)
        atomicAdd(&g_zero[__ldg(dst + i)], 1);
    for (int i = i0; i < 32768; i += gsz) {
        int nrow = i >> 8, k = i & 255;
        int widx = nrow * 128 + (k & 127);
        float w0 = (k < 128) ? __ldg(Wl0 + widx) : __ldg(Wr0 + widx);
        float w1 = (k < 128) ? __ldg(Wl1 + widx) : __ldg(Wr1 + widx);
        g_w16a[nrow * 256 + k] = __float2half_rn(w0);
        g_w16b[nrow * 256 + k] = __float2half_rn(w1);
    }
}

// ---------------- K2: single-pass scan (decoupled lookback) -----------------
__global__ void scan_lb(int n, int E) {
    __shared__ int s[1024];
    __shared__ int sbid, sprev;
    int tid = threadIdx.x;
    if (tid == 0) sbid = atomicAdd(&g_zero[ZF_TKT], 1);
    __syncthreads();
    int bid = sbid;
    int i = bid * 1024 + tid;
    int v = (i < n) ? g_zero[i] : 0;
    s[tid] = v;
    __syncthreads();
    for (int off = 1; off < 1024; off <<= 1) {
        int t = (tid >= off) ? s[tid - off] : 0;
        __syncthreads();
        s[tid] += t;
        __syncthreads();
    }
    if (tid == 0) {
        int total = s[1023];
        if (bid == 0) {
            atomicExch(&g_zero[ZF_INC + 0], total);
            __threadfence();
            atomicExch(&g_zero[ZF_FLAG + 0], 2);
            sprev = 0;
        } else {
            atomicExch(&g_zero[ZF_AGG + bid], total);
            __threadfence();
            atomicExch(&g_zero[ZF_FLAG + bid], 1);
            int prev = 0, j = bid - 1;
            while (1) {
                int f;
                do { f = atomicAdd(&g_zero[ZF_FLAG + j], 0); } while (f == 0);
                if (f == 2) { prev += atomicAdd(&g_zero[ZF_INC + j], 0); break; }
                prev += atomicAdd(&g_zero[ZF_AGG + j], 0);
                --j;
            }
            atomicExch(&g_zero[ZF_INC + bid], prev + total);
            __threadfence();
            atomicExch(&g_zero[ZF_FLAG + bid], 2);
            sprev = prev;
        }
    }
    __syncthreads();
    int off = sprev + s[tid] - v;   // exclusive prefix
    if (i < n) { g_off[i] = off; g_cur[i] = off; }
    if (i == n) g_off[n] = E;
}

// ---------------- K3: CSR fill (int4 edge loads) -----------------------------
__global__ void fill_kernel(const int* __restrict__ src,
                            const int* __restrict__ dst, int E) {
    int i = blockIdx.x * blockDim.x + threadIdx.x;
    int stride = gridDim.x * blockDim.x;
    int E4 = E >> 2;
    for (int j = i; j < E4; j += stride) {
        int4 s4 = __ldg(((const int4*)src) + j);
        int4 d4 = __ldg(((const int4*)dst) + j);
        g_csr[atomicAdd(&g_cur[d4.x], 1)] = s4.x;
        g_csr[atomicAdd(&g_cur[d4.y], 1)] = s4.y;
        g_csr[atomicAdd(&g_cur[d4.z], 1)] = s4.z;
        g_csr[atomicAdd(&g_cur[d4.w], 1)] = s4.w;
    }
    for (int j = E4 * 4 + i; j < E; j += stride) {
        int pos = atomicAdd(&g_cur[dst[j]], 1);
        g_csr[pos] = src[j];
    }
}

// ---------------- mean gather: fp16 pair-adds, high occupancy ---------------
__global__ void gather_mean(const __half* __restrict__ h, int n) {
    int lane = threadIdx.x & 31;
    int w = (blockIdx.x * blockDim.x + threadIdx.x) >> 5;
    int nw = (gridDim.x * blockDim.x) >> 5;
    const uint2* hb = ((const uint2*)h) + lane;   // row r -> hb[r*32]
    for (int i = w; i < n; i += nw) {
        int beg = g_off[i], end = g_off[i + 1];
        float4 acc = make_float4(0.f, 0.f, 0.f, 0.f);
        int e = beg;
        for (; e + 3 < end; e += 4) {
            int s0 = __ldg(g_csr + e);
            int s1 = __ldg(g_csr + e + 1);
            int s2 = __ldg(g_csr + e + 2);
            int s3 = __ldg(g_csr + e + 3);
            uint2 r0 = __ldg(hb + s0 * 32);
            uint2 r1 = __ldg(hb + s1 * 32);
            uint2 r2 = __ldg(hb + s2 * 32);
            uint2 r3 = __ldg(hb + s3 * 32);
            __half2 p0 = __hadd2(*(__half2*)&r0.x, *(__half2*)&r1.x);
            __half2 p1 = __hadd2(*(__half2*)&r0.y, *(__half2*)&r1.y);
            __half2 q0 = __hadd2(*(__half2*)&r2.x, *(__half2*)&r3.x);
            __half2 q1 = __hadd2(*(__half2*)&r2.y, *(__half2*)&r3.y);
            float2 fp0 = __half22float2(p0);
            float2 fp1 = __half22float2(p1);
            float2 fq0 = __half22float2(q0);
            float2 fq1 = __half22float2(q1);
            acc.x += fp0.x + fq0.x;
            acc.y += fp0.y + fq0.y;
            acc.z += fp1.x + fq1.x;
            acc.w += fp1.y + fq1.y;
        }
        if (e + 1 < end) {
            int s0 = __ldg(g_csr + e);
            int s1 = __ldg(g_csr + e + 1);
            uint2 r0 = __ldg(hb + s0 * 32);
            uint2 r1 = __ldg(hb + s1 * 32);
            __half2 p0 = __hadd2(*(__half2*)&r0.x, *(__half2*)&r1.x);
            __half2 p1 = __hadd2(*(__half2*)&r0.y, *(__half2*)&r1.y);
            float2 fp0 = __half22float2(p0);
            float2 fp1 = __half22float2(p1);
            acc.x += fp0.x; acc.y += fp0.y; acc.z += fp1.x; acc.w += fp1.y;
            e += 2;
        }
        if (e < end) {
            int s = __ldg(g_csr + e);
            uint2 raw = __ldg(hb + s * 32);
            float2 f01 = __half22float2(*(__half2*)&raw.x);
            float2 f23 = __half22float2(*(__half2*)&raw.y);
            acc.x += f01.x; acc.y += f01.y; acc.z += f23.x; acc.w += f23.y;
        }
        float inv = 1.0f / fmaxf((float)(end - beg), 1.0f);
        __half2 h01 = __floats2half2_rn(acc.x * inv, acc.y * inv);
        __half2 h23 = __floats2half2_rn(acc.z * inv, acc.w * inv);
        uint2 o;
        o.x = *(unsigned*)&h01;
        o.y = *(unsigned*)&h23;
        *((uint2*)(g_a16 + (size_t)i * D + lane * 4)) = o;
    }
}

// =============================================================================
// fp16 mma.sync GEMM (persistent): out[m][n] = relu(sum_k A[m][k] W[n][k] + b)
// K=256 (A = [agg | feat] fp16). Tile: 256 rows x 128 cols, 16 warps (8m x 2n),
// warp m32 x n64. W resident in smem; next A tile prefetched during epilogue.
// =============================================================================
#define GEMM_GRID 148
#define TM 256
#define SM_B    0        // W fp16 [128][264] (67584 B)
#define SM_A    67584    // A fp16 [256][264] (135168 B)
#define SM_RED  202752   // sS[256], sZ[256], sWl2[128], sWr2[128], sB[128]
#define GEMM_SMEM 206336

__device__ __forceinline__ unsigned su32(const void* p) {
    return (unsigned)__cvta_generic_to_shared(p);
}
__device__ __forceinline__ void cpa16(unsigned dst, const void* src, bool ok) {
    asm volatile("cp.async.cg.shared.global [%0], [%1], 16, %2;"
                 :: "r"(dst), "l"(src), "r"(ok ? 16 : 0));
}
__device__ __forceinline__ void ldm4(unsigned* r, unsigned addr) {
    asm volatile("ldmatrix.sync.aligned.m8n8.x4.shared.b16 {%0,%1,%2,%3}, [%4];"
                 : "=r"(r[0]), "=r"(r[1]), "=r"(r[2]), "=r"(r[3]) : "r"(addr));
}
__device__ __forceinline__ void mma16(float* d, const unsigned* a,
                                      unsigned b0, unsigned b1) {
    asm volatile(
        "mma.sync.aligned.m16n8k16.row.col.f32.f16.f16.f32 "
        "{%0,%1,%2,%3}, {%4,%5,%6,%7}, {%8,%9}, {%0,%1,%2,%3};"
        : "+f"(d[0]), "+f"(d[1]), "+f"(d[2]), "+f"(d[3])
        : "r"(a[0]), "r"(a[1]), "r"(a[2]), "r"(a[3]), "r"(b0), "r"(b1));
}

// A tile loader: 256 rows x 256 fp16 (row = [agg row | feat row]), 528B stride
__device__ __forceinline__ void loadA16(unsigned smb, int tid, int n, int tile,
                                        const __half* agg, const __half* feat) {
    #pragma unroll
    for (int u = tid; u < 8192; u += 512) {
        int r = u >> 5, seg = u & 31;
        int row = tile * TM + r;
        bool ok = row < n;
        const __half* srcb = (seg < 16) ? agg : feat;
        size_t off = (size_t)(ok ? row : 0) * 128 + (seg & 15) * 8;
        cpa16(smb + SM_A + r * 528 + seg * 16, srcb + off, ok);
    }
}

__global__ __launch_bounds__(512, 1) void gemm16(
    const __half* __restrict__ agg, const __half* __restrict__ feat,
    const __half* __restrict__ w16,
    const float* __restrict__ bias,
    __half* __restrict__ outF16,
    const float* __restrict__ Wl2, const float* __restrict__ Wr2,
    int n, int mode)
{
    extern __shared__ char sm[];
    unsigned smb = su32(sm);
    float* sS   = (float*)(sm + SM_RED);   // [256]
    float* sZ   = sS + 256;                // [256]
    float* sWl2 = sZ + 256;                // [128]
    float* sWr2 = sWl2 + 128;              // [128]
    float* sB   = sWr2 + 128;              // [128]

    int tid = threadIdx.x;
    int lane = tid & 31;
    int wid = tid >> 5;
    int mwarp = wid & 7;          // rows [mwarp*32, +32)
    int nwarp = wid >> 3;         // cols [nwarp*64, +64)
    int ntiles = (n + TM - 1) / TM;

    if (tid < 128) {
        sB[tid] = bias[tid];
        if (mode == 1) { sWl2[tid] = Wl2[tid]; sWr2[tid] = Wr2[tid]; }
    }

    // W resident load
    #pragma unroll
    for (int u = tid; u < 4096; u += 512) {
        int nrow = u >> 5, kc = u & 31;
        cpa16(smb + SM_B + nrow * 528 + kc * 16, w16 + nrow * 256 + kc * 8, true);
    }
    int t0 = blockIdx.x;
    if (t0 < ntiles) loadA16(smb, tid, n, t0, agg, feat);
    asm volatile("cp.async.commit_group;");

    // ldmatrix per-thread addresses
    unsigned aAddr = smb + SM_A
        + (mwarp * 32 + (lane & 7) + ((lane >> 3) & 1) * 8) * 528
        + ((lane >> 4) & 1) * 16;
    unsigned bAddr = smb + SM_B
        + (nwarp * 64 + (lane & 7) + ((lane >> 4) & 1) * 8) * 528
        + ((lane >> 3) & 1) * 16;

    int g = lane >> 2, tq = lane & 3;

    for (int t = t0; t < ntiles; t += gridDim.x) {
        if (mode == 1 && tid < 256) { sS[tid] = 0.f; sZ[tid] = 0.f; }

        asm volatile("cp.async.wait_group 0;");
        __syncthreads();

        float acc[2][8][4];
        #pragma unroll
        for (int h = 0; h < 2; ++h)
            #pragma unroll
            for (int i = 0; i < 8; ++i)
                #pragma unroll
                for (int j = 0; j < 4; ++j) acc[h][i][j] = 0.f;

        #pragma unroll
        for (int k = 0; k < 16; ++k) {
            unsigned a0[4], a1[4], b[4];
            ldm4(a0, aAddr + k * 32);
            ldm4(a1, aAddr + 16 * 528 + k * 32);
            #pragma unroll
            for (int p = 0; p < 4; ++p) {
                ldm4(b, bAddr + p * 16 * 528 + k * 32);
                mma16(acc[0][2 * p],     a0, b[0], b[1]);
                mma16(acc[0][2 * p + 1], a0, b[2], b[3]);
                mma16(acc[1][2 * p],     a1, b[0], b[1]);
                mma16(acc[1][2 * p + 1], a1, b[2], b[3]);
            }
        }
        __syncthreads();           // all warps done reading A smem

        int tn = t + gridDim.x;    // prefetch next tile during epilogue
        if (tn < ntiles) loadA16(smb, tid, n, tn, agg, feat);
        asm volatile("cp.async.commit_group;");

        // ---- epilogue ----
        #pragma unroll
        for (int h = 0; h < 2; ++h) {
            int r0 = t * TM + mwarp * 32 + h * 16 + g;
            int r1 = r0 + 8;
            float ps0 = 0.f, pz0 = 0.f, ps1 = 0.f, pz1 = 0.f;
            #pragma unroll
            for (int nt = 0; nt < 8; ++nt) {
                int col = nwarp * 64 + nt * 8 + tq * 2;
                float b0 = sB[col], b1 = sB[col + 1];
                float v0 = fmaxf(acc[h][nt][0] + b0, 0.f);
                float v1 = fmaxf(acc[h][nt][1] + b1, 0.f);
                float v2 = fmaxf(acc[h][nt][2] + b0, 0.f);
                float v3 = fmaxf(acc[h][nt][3] + b1, 0.f);
                if (mode == 0) {
                    if (r0 < n) {
                        __half2 f = __floats2half2_rn(v0, v1);
                        *((unsigned*)(outF16 + (size_t)r0 * D + col)) = *(unsigned*)&f;
                    }
                    if (r1 < n) {
                        __half2 f = __floats2half2_rn(v2, v3);
                        *((unsigned*)(outF16 + (size_t)r1 * D + col)) = *(unsigned*)&f;
                    }
                } else {
                    float wl0 = sWl2[col], wl1 = sWl2[col + 1];
                    float wr0 = sWr2[col], wr1 = sWr2[col + 1];
                    ps0 += v0 * wl0 + v1 * wl1;
                    pz0 += v0 * wr0 + v1 * wr1;
                    ps1 += v2 * wl0 + v3 * wl1;
                    pz1 += v2 * wr0 + v3 * wr1;
                }
            }
            if (mode == 1) {
                #pragma unroll
                for (int m = 1; m <= 2; m <<= 1) {
                    ps0 += __shfl_xor_sync(0xffffffffu, ps0, m);
                    pz0 += __shfl_xor_sync(0xffffffffu, pz0, m);
                    ps1 += __shfl_xor_sync(0xffffffffu, ps1, m);
                    pz1 += __shfl_xor_sync(0xffffffffu, pz1, m);
                }
                if (tq == 0) {
                    int lr = mwarp * 32 + h * 16 + g;
                    atomicAdd(&sS[lr], ps0);
                    atomicAdd(&sZ[lr], pz0);
                    atomicAdd(&sS[lr + 8], ps1);
                    atomicAdd(&sZ[lr + 8], pz1);
                }
            }
        }
        if (mode == 1) {
            __syncthreads();
            if (tid < 256) {
                int row = t * TM + tid;
                if (row < n) { g_s[row] = sS[tid]; g_z[row] = sZ[tid]; }
            }
        }
    }
}

// ---------------- final: mean-gather scalar + bias + sigmoid ----------------
__global__ void final_fused(const float* __restrict__ bl2,
                            float* __restrict__ out, int n) {
    int i = blockIdx.x * blockDim.x + threadIdx.x;
    if (i >= n) return;
    int beg = g_off[i], end = g_off[i + 1];
    float acc = 0.f;
    int e = beg;
    for (; e + 3 < end; e += 4) {
        float a0 = g_s[__ldg(g_csr + e)];
        float a1 = g_s[__ldg(g_csr + e + 1)];
        float a2 = g_s[__ldg(g_csr + e + 2)];
        float a3 = g_s[__ldg(g_csr + e + 3)];
        acc += (a0 + a1) + (a2 + a3);
    }
    for (; e < end; ++e) acc += g_s[__ldg(g_csr + e)];
    float v = acc / fmaxf((float)(end - beg), 1.0f) + __ldg(bl2) + g_z[i];
    out[i] = v;
    out[n + i] = 1.0f / (1.0f + expf(-v));
}

// ---------------------------------------------------------------------------
extern "C" void kernel_launch(void* const* d_in, const int* in_sizes, int n_in,
                              void* d_out, int out_size) {
    const float* x   = (const float*)d_in[0];
    const int*   ei  = (const int*)d_in[1];
    const float* Wl0 = (const float*)d_in[2];
    const float* bl0 = (const float*)d_in[3];
    const float* Wr0 = (const float*)d_in[4];
    const float* Wl1 = (const float*)d_in[5];
    const float* bl1 = (const float*)d_in[6];
    const float* Wr1 = (const float*)d_in[7];
    const float* Wl2 = (const float*)d_in[8];
    const float* bl2 = (const float*)d_in[9];
    const float* Wr2 = (const float*)d_in[10];
    float* out = (float*)d_out;

    int n = in_sizes[0] / D;   // 100000
    int E = in_sizes[1] / 2;   // 1600000
    const int* src = ei;
    const int* dst = ei + E;

    void* p_zero;
    cudaGetSymbolAddress(&p_zero, g_zero);
    __half *a16, *f16, *w16a, *w16b;
    cudaGetSymbolAddress((void**)&a16, g_a16);
    cudaGetSymbolAddress((void**)&f16, g_f16);
    cudaGetSymbolAddress((void**)&w16a, g_w16a);
    cudaGetSymbolAddress((void**)&w16b, g_w16b);

    cudaFuncSetAttribute(gemm16, cudaFuncAttributeMaxDynamicSharedMemorySize,
                         GEMM_SMEM);

    int scan_blocks = (n + 1024) / 1024;       // 98 (covers i==n too)
    int fill_blocks = ((E >> 2) + 255) / 256;  // 1563

    // zero cnt + scan state; fused convert/count/prep; scan; fill
    cudaMemsetAsync(p_zero, 0, (size_t)(NN + 385) * sizeof(int));
    prep_all<<<12500, 256>>>(x, dst, Wl0, Wr0, Wl1, Wr1, n, E);
    scan_lb<<<scan_blocks, 1024>>>(n, E);
    fill_kernel<<<fill_blocks, 256>>>(src, dst, E);

    // Layer 0
    gather_mean<<<12500, 256>>>(f16, n);
    gemm16<<<GEMM_GRID, 512, GEMM_SMEM>>>(a16, f16, w16a, bl0, f16,
                                          (const float*)0, (const float*)0,
                                          n, 0);

    // Layer 1 (+ fused layer-2 scalarization: s = h2·Wl2, z = h2·Wr2)
    gather_mean<<<12500, 256>>>(f16, n);
    gemm16<<<GEMM_GRID, 512, GEMM_SMEM>>>(a16, f16, w16b, bl1, (__half*)0,
                                          Wl2, Wr2, n, 1);

    // Layer 2 aggregation + output
    final_fused<<<(n + 255) / 256, 256>>>(bl2, out, n);
}

// round 14
// speedup vs baseline: 1.4848x; 1.0184x over previous
#include <cuda_runtime.h>
#include <cuda_fp16.h>
#include <stdint.h>
#include <math.h>

#define NN 100000
#define EE 1600000
#define D  128
#define CSR_CAP (EE + 4 * NN)

// ---------------- device scratch (no allocations allowed) -------------------
// g_f16 has one extra all-zero row at index NN (never written; static zero)
__device__ __align__(16) __half g_a16[(size_t)NN * D];         // agg fp16
__device__ __align__(16) __half g_f16[(size_t)(NN + 1) * D];   // feat fp16
__device__ __align__(16) __half g_w16a[128 * 256];             // [Wl0;Wr0]
__device__ __align__(16) __half g_w16b[128 * 256];             // [Wl1;Wr1]
// zeroed-each-call region: cnt[NN], flag[128], agg[128], inc[128], ticket
__device__ int g_zero[NN + 385];
#define ZF_FLAG  (NN)
#define ZF_AGG   (NN + 128)
#define ZF_INC   (NN + 256)
#define ZF_TKT   (NN + 384)
__device__ int g_off[NN + 1];
__device__ int g_cur[NN];
__device__ __align__(16) int g_csr[CSR_CAP];
__device__ float g_s[NN + 1];   // g_s[NN] = 0 (static, never written)
__device__ float g_z[NN];

// ---------------- K1: convert_x + edge count (int4) + weight prep -----------
__global__ void prep_all(const float* __restrict__ x,
                         const int* __restrict__ dst,
                         const float* __restrict__ Wl0, const float* __restrict__ Wr0,
                         const float* __restrict__ Wl1, const float* __restrict__ Wr1,
                         int n, int E) {
    int gsz = gridDim.x * blockDim.x;
    int i0 = blockIdx.x * blockDim.x + threadIdx.x;

    int n4 = n * 32;
    for (int i = i0; i < n4; i += gsz) {
        float4 v = __ldg(((const float4*)x) + i);
        __half2 a = __floats2half2_rn(v.x, v.y);
        __half2 b = __floats2half2_rn(v.z, v.w);
        uint2 F;
        F.x = *(unsigned*)&a;
        F.y = *(unsigned*)&b;
        *((uint2*)(g_f16 + (size_t)i * 4)) = F;
    }
    int E4 = E >> 2;
    for (int i = i0; i < E4; i += gsz) {
        int4 d4 = __ldg(((const int4*)dst) + i);
        atomicAdd(&g_zero[d4.x], 1);
        atomicAdd(&g_zero[d4.y], 1);
        atomicAdd(&g_zero[d4.z], 1);
        atomicAdd(&g_zero[d4.w], 1);
    }
    for (int i = E4 * 4 + i0; i < E; i += gsz)
        atomicAdd(&g_zero[__ldg(dst + i)], 1);
    for (int i = i0; i < 32768; i += gsz) {
        int nrow = i >> 8, k = i & 255;
        int widx = nrow * 128 + (k & 127);
        float w0 = (k < 128) ? __ldg(Wl0 + widx) : __ldg(Wr0 + widx);
        float w1 = (k < 128) ? __ldg(Wl1 + widx) : __ldg(Wr1 + widx);
        g_w16a[nrow * 256 + k] = __float2half_rn(w0);
        g_w16b[nrow * 256 + k] = __float2half_rn(w1);
    }
}

// ---------------- K2: scan of PADDED counts (decoupled lookback) ------------
// offsets are multiples of 4; pad slots get index n (zero feature row)
__global__ void scan_lb(int n) {
    __shared__ int s[1024];
    __shared__ int sbid, sprev;
    int tid = threadIdx.x;
    if (tid == 0) sbid = atomicAdd(&g_zero[ZF_TKT], 1);
    __syncthreads();
    int bid = sbid;
    int i = bid * 1024 + tid;
    int cnt = (i < n) ? g_zero[i] : 0;
    int v = (cnt + 3) & ~3;          // padded count
    s[tid] = v;
    __syncthreads();
    for (int off = 1; off < 1024; off <<= 1) {
        int t = (tid >= off) ? s[tid - off] : 0;
        __syncthreads();
        s[tid] += t;
        __syncthreads();
    }
    if (tid == 0) {
        int total = s[1023];
        if (bid == 0) {
            atomicExch(&g_zero[ZF_INC + 0], total);
            __threadfence();
            atomicExch(&g_zero[ZF_FLAG + 0], 2);
            sprev = 0;
        } else {
            atomicExch(&g_zero[ZF_AGG + bid], total);
            __threadfence();
            atomicExch(&g_zero[ZF_FLAG + bid], 1);
            int prev = 0, j = bid - 1;
            while (1) {
                int f;
                do { f = atomicAdd(&g_zero[ZF_FLAG + j], 0); } while (f == 0);
                if (f == 2) { prev += atomicAdd(&g_zero[ZF_INC + j], 0); break; }
                prev += atomicAdd(&g_zero[ZF_AGG + j], 0);
                --j;
            }
            atomicExch(&g_zero[ZF_INC + bid], prev + total);
            __threadfence();
            atomicExch(&g_zero[ZF_FLAG + bid], 2);
            sprev = prev;
        }
    }
    __syncthreads();
    int off = sprev + s[tid] - v;   // exclusive padded prefix
    if (i < n) {
        g_off[i] = off;
        g_cur[i] = off;
        // write pad slots -> zero-row index n
        for (int j = off + cnt; j < off + v; ++j) g_csr[j] = n;
    }
    if (i == n) g_off[n] = off;     // padded total
}

// ---------------- K3: CSR fill (int4 edge loads) -----------------------------
__global__ void fill_kernel(const int* __restrict__ src,
                            const int* __restrict__ dst, int E) {
    int i = blockIdx.x * blockDim.x + threadIdx.x;
    int stride = gridDim.x * blockDim.x;
    int E4 = E >> 2;
    for (int j = i; j < E4; j += stride) {
        int4 s4 = __ldg(((const int4*)src) + j);
        int4 d4 = __ldg(((const int4*)dst) + j);
        g_csr[atomicAdd(&g_cur[d4.x], 1)] = s4.x;
        g_csr[atomicAdd(&g_cur[d4.y], 1)] = s4.y;
        g_csr[atomicAdd(&g_cur[d4.z], 1)] = s4.z;
        g_csr[atomicAdd(&g_cur[d4.w], 1)] = s4.w;
    }
    for (int j = E4 * 4 + i; j < E; j += stride) {
        int pos = atomicAdd(&g_cur[dst[j]], 1);
        g_csr[pos] = src[j];
    }
}

// ---------------- mean gather: padded CSR, int4 idx, no tails ---------------
__global__ void gather_mean(const __half* __restrict__ h, int n) {
    int lane = threadIdx.x & 31;
    int w = (blockIdx.x * blockDim.x + threadIdx.x) >> 5;
    int nw = (gridDim.x * blockDim.x) >> 5;
    const uint2* hb = ((const uint2*)h) + lane;   // row r -> hb[r*32]
    for (int i = w; i < n; i += nw) {
        int beg = g_off[i];
        int n4 = (g_off[i + 1] - beg) >> 2;       // groups of 4 (exact)
        const int4* c4 = (const int4*)(g_csr + beg);
        float4 acc = make_float4(0.f, 0.f, 0.f, 0.f);
        #pragma unroll 2
        for (int j = 0; j < n4; ++j) {
            int4 s4 = __ldg(c4 + j);
            uint2 r0 = __ldg(hb + s4.x * 32);
            uint2 r1 = __ldg(hb + s4.y * 32);
            uint2 r2 = __ldg(hb + s4.z * 32);
            uint2 r3 = __ldg(hb + s4.w * 32);
            __half2 p0 = __hadd2(*(__half2*)&r0.x, *(__half2*)&r1.x);
            __half2 p1 = __hadd2(*(__half2*)&r0.y, *(__half2*)&r1.y);
            __half2 q0 = __hadd2(*(__half2*)&r2.x, *(__half2*)&r3.x);
            __half2 q1 = __hadd2(*(__half2*)&r2.y, *(__half2*)&r3.y);
            float2 fp0 = __half22float2(p0);
            float2 fp1 = __half22float2(p1);
            float2 fq0 = __half22float2(q0);
            float2 fq1 = __half22float2(q1);
            acc.x += fp0.x + fq0.x;
            acc.y += fp0.y + fq0.y;
            acc.z += fp1.x + fq1.x;
            acc.w += fp1.y + fq1.y;
        }
        float inv = 1.0f / fmaxf((float)g_zero[i], 1.0f);   // true degree
        __half2 h01 = __floats2half2_rn(acc.x * inv, acc.y * inv);
        __half2 h23 = __floats2half2_rn(acc.z * inv, acc.w * inv);
        uint2 o;
        o.x = *(unsigned*)&h01;
        o.y = *(unsigned*)&h23;
        *((uint2*)(g_a16 + (size_t)i * D + lane * 4)) = o;
    }
}

// =============================================================================
// fp16 mma.sync GEMM (persistent): out[m][n] = relu(sum_k A[m][k] W[n][k] + b)
// K=256 (A = [agg | feat] fp16). Tile: 256 rows x 128 cols, 16 warps (8m x 2n),
// warp m32 x n64. W resident in smem; next A tile prefetched during epilogue.
// =============================================================================
#define GEMM_GRID 148
#define TM 256
#define SM_B    0        // W fp16 [128][264] (67584 B)
#define SM_A    67584    // A fp16 [256][264] (135168 B)
#define SM_RED  202752   // sS[256], sZ[256], sWl2[128], sWr2[128], sB[128]
#define GEMM_SMEM 206336

__device__ __forceinline__ unsigned su32(const void* p) {
    return (unsigned)__cvta_generic_to_shared(p);
}
__device__ __forceinline__ void cpa16(unsigned dst, const void* src, bool ok) {
    asm volatile("cp.async.cg.shared.global [%0], [%1], 16, %2;"
                 :: "r"(dst), "l"(src), "r"(ok ? 16 : 0));
}
__device__ __forceinline__ void ldm4(unsigned* r, unsigned addr) {
    asm volatile("ldmatrix.sync.aligned.m8n8.x4.shared.b16 {%0,%1,%2,%3}, [%4];"
                 : "=r"(r[0]), "=r"(r[1]), "=r"(r[2]), "=r"(r[3]) : "r"(addr));
}
__device__ __forceinline__ void mma16(float* d, const unsigned* a,
                                      unsigned b0, unsigned b1) {
    asm volatile(
        "mma.sync.aligned.m16n8k16.row.col.f32.f16.f16.f32 "
        "{%0,%1,%2,%3}, {%4,%5,%6,%7}, {%8,%9}, {%0,%1,%2,%3};"
        : "+f"(d[0]), "+f"(d[1]), "+f"(d[2]), "+f"(d[3])
        : "r"(a[0]), "r"(a[1]), "r"(a[2]), "r"(a[3]), "r"(b0), "r"(b1));
}

// A tile loader: 256 rows x 256 fp16 (row = [agg row | feat row]), 528B stride
__device__ __forceinline__ void loadA16(unsigned smb, int tid, int n, int tile,
                                        const __half* agg, const __half* feat) {
    #pragma unroll
    for (int u = tid; u < 8192; u += 512) {
        int r = u >> 5, seg = u & 31;
        int row = tile * TM + r;
        bool ok = row < n;
        const __half* srcb = (seg < 16) ? agg : feat;
        size_t off = (size_t)(ok ? row : 0) * 128 + (seg & 15) * 8;
        cpa16(smb + SM_A + r * 528 + seg * 16, srcb + off, ok);
    }
}

__global__ __launch_bounds__(512, 1) void gemm16(
    const __half* __restrict__ agg, const __half* __restrict__ feat,
    const __half* __restrict__ w16,
    const float* __restrict__ bias,
    __half* __restrict__ outF16,
    const float* __restrict__ Wl2, const float* __restrict__ Wr2,
    int n, int mode)
{
    extern __shared__ char sm[];
    unsigned smb = su32(sm);
    float* sS   = (float*)(sm + SM_RED);   // [256]
    float* sZ   = sS + 256;                // [256]
    float* sWl2 = sZ + 256;                // [128]
    float* sWr2 = sWl2 + 128;              // [128]
    float* sB   = sWr2 + 128;              // [128]

    int tid = threadIdx.x;
    int lane = tid & 31;
    int wid = tid >> 5;
    int mwarp = wid & 7;          // rows [mwarp*32, +32)
    int nwarp = wid >> 3;         // cols [nwarp*64, +64)
    int ntiles = (n + TM - 1) / TM;

    if (tid < 128) {
        sB[tid] = bias[tid];
        if (mode == 1) { sWl2[tid] = Wl2[tid]; sWr2[tid] = Wr2[tid]; }
    }

    // W resident load
    #pragma unroll
    for (int u = tid; u < 4096; u += 512) {
        int nrow = u >> 5, kc = u & 31;
        cpa16(smb + SM_B + nrow * 528 + kc * 16, w16 + nrow * 256 + kc * 8, true);
    }
    int t0 = blockIdx.x;
    if (t0 < ntiles) loadA16(smb, tid, n, t0, agg, feat);
    asm volatile("cp.async.commit_group;");

    // ldmatrix per-thread addresses
    unsigned aAddr = smb + SM_A
        + (mwarp * 32 + (lane & 7) + ((lane >> 3) & 1) * 8) * 528
        + ((lane >> 4) & 1) * 16;
    unsigned bAddr = smb + SM_B
        + (nwarp * 64 + (lane & 7) + ((lane >> 4) & 1) * 8) * 528
        + ((lane >> 3) & 1) * 16;

    int g = lane >> 2, tq = lane & 3;

    for (int t = t0; t < ntiles; t += gridDim.x) {
        if (mode == 1 && tid < 256) { sS[tid] = 0.f; sZ[tid] = 0.f; }

        asm volatile("cp.async.wait_group 0;");
        __syncthreads();

        float acc[2][8][4];
        #pragma unroll
        for (int h = 0; h < 2; ++h)
            #pragma unroll
            for (int i = 0; i < 8; ++i)
                #pragma unroll
                for (int j = 0; j < 4; ++j) acc[h][i][j] = 0.f;

        #pragma unroll
        for (int k = 0; k < 16; ++k) {
            unsigned a0[4], a1[4], b[4];
            ldm4(a0, aAddr + k * 32);
            ldm4(a1, aAddr + 16 * 528 + k * 32);
            #pragma unroll
            for (int p = 0; p < 4; ++p) {
                ldm4(b, bAddr + p * 16 * 528 + k * 32);
                mma16(acc[0][2 * p],     a0, b[0], b[1]);
                mma16(acc[0][2 * p + 1], a0, b[2], b[3]);
                mma16(acc[1][2 * p],     a1, b[0], b[1]);
                mma16(acc[1][2 * p + 1], a1, b[2], b[3]);
            }
        }
        __syncthreads();           // all warps done reading A smem

        int tn = t + gridDim.x;    // prefetch next tile during epilogue
        if (tn < ntiles) loadA16(smb, tid, n, tn, agg, feat);
        asm volatile("cp.async.commit_group;");

        // ---- epilogue ----
        #pragma unroll
        for (int h = 0; h < 2; ++h) {
            int r0 = t * TM + mwarp * 32 + h * 16 + g;
            int r1 = r0 + 8;
            float ps0 = 0.f, pz0 = 0.f, ps1 = 0.f, pz1 = 0.f;
            #pragma unroll
            for (int nt = 0; nt < 8; ++nt) {
                int col = nwarp * 64 + nt * 8 + tq * 2;
                float b0 = sB[col], b1 = sB[col + 1];
                float v0 = fmaxf(acc[h][nt][0] + b0, 0.f);
                float v1 = fmaxf(acc[h][nt][1] + b1, 0.f);
                float v2 = fmaxf(acc[h][nt][2] + b0, 0.f);
                float v3 = fmaxf(acc[h][nt][3] + b1, 0.f);
                if (mode == 0) {
                    if (r0 < n) {
                        __half2 f = __floats2half2_rn(v0, v1);
                        *((unsigned*)(outF16 + (size_t)r0 * D + col)) = *(unsigned*)&f;
                    }
                    if (r1 < n) {
                        __half2 f = __floats2half2_rn(v2, v3);
                        *((unsigned*)(outF16 + (size_t)r1 * D + col)) = *(unsigned*)&f;
                    }
                } else {
                    float wl0 = sWl2[col], wl1 = sWl2[col + 1];
                    float wr0 = sWr2[col], wr1 = sWr2[col + 1];
                    ps0 += v0 * wl0 + v1 * wl1;
                    pz0 += v0 * wr0 + v1 * wr1;
                    ps1 += v2 * wl0 + v3 * wl1;
                    pz1 += v2 * wr0 + v3 * wr1;
                }
            }
            if (mode == 1) {
                #pragma unroll
                for (int m = 1; m <= 2; m <<= 1) {
                    ps0 += __shfl_xor_sync(0xffffffffu, ps0, m);
                    pz0 += __shfl_xor_sync(0xffffffffu, pz0, m);
                    ps1 += __shfl_xor_sync(0xffffffffu, ps1, m);
                    pz1 += __shfl_xor_sync(0xffffffffu, pz1, m);
                }
                if (tq == 0) {
                    int lr = mwarp * 32 + h * 16 + g;
                    atomicAdd(&sS[lr], ps0);
                    atomicAdd(&sZ[lr], pz0);
                    atomicAdd(&sS[lr + 8], ps1);
                    atomicAdd(&sZ[lr + 8], pz1);
                }
            }
        }
        if (mode == 1) {
            __syncthreads();
            if (tid < 256) {
                int row = t * TM + tid;
                if (row < n) { g_s[row] = sS[tid]; g_z[row] = sZ[tid]; }
            }
        }
    }
}

// ---------------- final: mean-gather scalar + bias + sigmoid ----------------
__global__ void final_fused(const float* __restrict__ bl2,
                            float* __restrict__ out, int n) {
    int i = blockIdx.x * blockDim.x + threadIdx.x;
    if (i >= n) return;
    int beg = g_off[i];
    int n4 = (g_off[i + 1] - beg) >> 2;
    const int4* c4 = (const int4*)(g_csr + beg);
    float acc = 0.f;
    for (int j = 0; j < n4; ++j) {
        int4 s4 = __ldg(c4 + j);
        acc += (g_s[s4.x] + g_s[s4.y]) + (g_s[s4.z] + g_s[s4.w]);
    }
    float v = acc / fmaxf((float)g_zero[i], 1.0f) + __ldg(bl2) + g_z[i];
    out[i] = v;
    out[n + i] = 1.0f / (1.0f + expf(-v));
}

// ---------------------------------------------------------------------------
extern "C" void kernel_launch(void* const* d_in, const int* in_sizes, int n_in,
                              void* d_out, int out_size) {
    const float* x   = (const float*)d_in[0];
    const int*   ei  = (const int*)d_in[1];
    const float* Wl0 = (const float*)d_in[2];
    const float* bl0 = (const float*)d_in[3];
    const float* Wr0 = (const float*)d_in[4];
    const float* Wl1 = (const float*)d_in[5];
    const float* bl1 = (const float*)d_in[6];
    const float* Wr1 = (const float*)d_in[7];
    const float* Wl2 = (const float*)d_in[8];
    const float* bl2 = (const float*)d_in[9];
    const float* Wr2 = (const float*)d_in[10];
    float* out = (float*)d_out;

    int n = in_sizes[0] / D;   // 100000
    int E = in_sizes[1] / 2;   // 1600000
    const int* src = ei;
    const int* dst = ei + E;

    void* p_zero;
    cudaGetSymbolAddress(&p_zero, g_zero);
    __half *a16, *f16, *w16a, *w16b;
    cudaGetSymbolAddress((void**)&a16, g_a16);
    cudaGetSymbolAddress((void**)&f16, g_f16);
    cudaGetSymbolAddress((void**)&w16a, g_w16a);
    cudaGetSymbolAddress((void**)&w16b, g_w16b);

    cudaFuncSetAttribute(gemm16, cudaFuncAttributeMaxDynamicSharedMemorySize,
                         GEMM_SMEM);

    int scan_blocks = (n + 1024) / 1024;       // 98 (covers i==n too)
    int fill_blocks = ((E >> 2) + 255) / 256;  // 1563

    // zero cnt + scan state; fused convert/count/prep; padded scan; fill
    cudaMemsetAsync(p_zero, 0, (size_t)(NN + 385) * sizeof(int));
    prep_all<<<12500, 256>>>(x, dst, Wl0, Wr0, Wl1, Wr1, n, E);
    scan_lb<<<scan_blocks, 1024>>>(n);
    fill_kernel<<<fill_blocks, 256>>>(src, dst, E);

    // Layer 0
    gather_mean<<<12500, 256>>>(f16, n);
    gemm16<<<GEMM_GRID, 512, GEMM_SMEM>>>(a16, f16, w16a, bl0, f16,
                                          (const float*)0, (const float*)0,
                                          n, 0);

    // Layer 1 (+ fused layer-2 scalarization: s = h2·Wl2, z = h2·Wr2)
    gather_mean<<<12500, 256>>>(f16, n);
    gemm16<<<GEMM_GRID, 512, GEMM_SMEM>>>(a16, f16, w16b, bl1, (__half*)0,
                                          Wl2, Wr2, n, 1);

    // Layer 2 aggregation + output
    final_fused<<<(n + 255) / 256, 256>>>(bl2, out, n);
}

// round 15
// speedup vs baseline: 1.4856x; 1.0005x over previous
#include <cuda_runtime.h>
#include <cuda_fp16.h>
#include <stdint.h>
#include <math.h>

#define NN 100000
#define EE 1600000
#define D  128
#define CSR_CAP (EE + 4 * NN)

// ---------------- device scratch (no allocations allowed) -------------------
// g_f16 has one extra all-zero row at index NN (never written; static zero)
__device__ __align__(16) __half g_a16[(size_t)NN * D];         // agg fp16
__device__ __align__(16) __half g_f16[(size_t)(NN + 1) * D];   // feat fp16
__device__ __align__(16) __half g_w16a[128 * 256];             // [Wl0;Wr0]
__device__ __align__(16) __half g_w16b[128 * 256];             // [Wl1;Wr1]
// zeroed-each-call region: cnt[NN], flag[128], agg[128], inc[128], ticket
__device__ int g_zero[NN + 385];
#define ZF_FLAG  (NN)
#define ZF_AGG   (NN + 128)
#define ZF_INC   (NN + 256)
#define ZF_TKT   (NN + 384)
__device__ int g_off[NN + 1];
__device__ int g_cur[NN];
__device__ __align__(16) int g_csr[CSR_CAP];
__device__ float g_s[NN + 1];   // g_s[NN] = 0 (static, never written)
__device__ float g_z[NN];

// ---------------- K1: edge degree count (int4) ------------------------------
__global__ void count_kernel(const int* __restrict__ dst, int E) {
    int i = blockIdx.x * blockDim.x + threadIdx.x;
    int stride = gridDim.x * blockDim.x;
    int E4 = E >> 2;
    for (int j = i; j < E4; j += stride) {
        int4 d4 = __ldg(((const int4*)dst) + j);
        atomicAdd(&g_zero[d4.x], 1);
        atomicAdd(&g_zero[d4.y], 1);
        atomicAdd(&g_zero[d4.z], 1);
        atomicAdd(&g_zero[d4.w], 1);
    }
    for (int j = E4 * 4 + i; j < E; j += stride)
        atomicAdd(&g_zero[__ldg(dst + j)], 1);
}

// ---------------- K2: scan of PADDED counts (decoupled lookback) ------------
// offsets are multiples of 4; pad slots get index n (zero feature row)
__global__ void scan_lb(int n) {
    __shared__ int s[1024];
    __shared__ int sbid, sprev;
    int tid = threadIdx.x;
    if (tid == 0) sbid = atomicAdd(&g_zero[ZF_TKT], 1);
    __syncthreads();
    int bid = sbid;
    int i = bid * 1024 + tid;
    int cnt = (i < n) ? g_zero[i] : 0;
    int v = (cnt + 3) & ~3;          // padded count
    s[tid] = v;
    __syncthreads();
    for (int off = 1; off < 1024; off <<= 1) {
        int t = (tid >= off) ? s[tid - off] : 0;
        __syncthreads();
        s[tid] += t;
        __syncthreads();
    }
    if (tid == 0) {
        int total = s[1023];
        if (bid == 0) {
            atomicExch(&g_zero[ZF_INC + 0], total);
            __threadfence();
            atomicExch(&g_zero[ZF_FLAG + 0], 2);
            sprev = 0;
        } else {
            atomicExch(&g_zero[ZF_AGG + bid], total);
            __threadfence();
            atomicExch(&g_zero[ZF_FLAG + bid], 1);
            int prev = 0, j = bid - 1;
            while (1) {
                int f;
                do { f = atomicAdd(&g_zero[ZF_FLAG + j], 0); } while (f == 0);
                if (f == 2) { prev += atomicAdd(&g_zero[ZF_INC + j], 0); break; }
                prev += atomicAdd(&g_zero[ZF_AGG + j], 0);
                --j;
            }
            atomicExch(&g_zero[ZF_INC + bid], prev + total);
            __threadfence();
            atomicExch(&g_zero[ZF_FLAG + bid], 2);
            sprev = prev;
        }
    }
    __syncthreads();
    int off = sprev + s[tid] - v;   // exclusive padded prefix
    if (i < n) {
        g_off[i] = off;
        g_cur[i] = off;
        for (int j = off + cnt; j < off + v; ++j) g_csr[j] = n;  // pad -> zero row
    }
    if (i == n) g_off[n] = off;     // padded total
}

// ---------------- K3: fill (atomic/L2) + convert_x (DRAM) + weights, fused --
__global__ void build_all(const int* __restrict__ src,
                          const int* __restrict__ dst,
                          const float* __restrict__ x,
                          const float* __restrict__ Wl0, const float* __restrict__ Wr0,
                          const float* __restrict__ Wl1, const float* __restrict__ Wr1,
                          int n, int E) {
    int gsz = gridDim.x * blockDim.x;
    int i0 = blockIdx.x * blockDim.x + threadIdx.x;

    // CSR fill (int4) — L2-atomic bound
    int E4 = E >> 2;
    for (int j = i0; j < E4; j += gsz) {
        int4 s4 = __ldg(((const int4*)src) + j);
        int4 d4 = __ldg(((const int4*)dst) + j);
        g_csr[atomicAdd(&g_cur[d4.x], 1)] = s4.x;
        g_csr[atomicAdd(&g_cur[d4.y], 1)] = s4.y;
        g_csr[atomicAdd(&g_cur[d4.z], 1)] = s4.z;
        g_csr[atomicAdd(&g_cur[d4.w], 1)] = s4.w;
    }
    for (int j = E4 * 4 + i0; j < E; j += gsz) {
        int pos = atomicAdd(&g_cur[dst[j]], 1);
        g_csr[pos] = src[j];
    }

    // x -> fp16 — DRAM bound (overlaps with atomics above across the grid)
    int n4 = n * 32;
    for (int i = i0; i < n4; i += gsz) {
        float4 v = __ldg(((const float4*)x) + i);
        __half2 a = __floats2half2_rn(v.x, v.y);
        __half2 b = __floats2half2_rn(v.z, v.w);
        uint2 F;
        F.x = *(unsigned*)&a;
        F.y = *(unsigned*)&b;
        *((uint2*)(g_f16 + (size_t)i * 4)) = F;
    }

    // weights (both layers) -> fp16 [n][k], k = [Wl | Wr]
    for (int i = i0; i < 32768; i += gsz) {
        int nrow = i >> 8, k = i & 255;
        int widx = nrow * 128 + (k & 127);
        float w0 = (k < 128) ? __ldg(Wl0 + widx) : __ldg(Wr0 + widx);
        float w1 = (k < 128) ? __ldg(Wl1 + widx) : __ldg(Wr1 + widx);
        g_w16a[nrow * 256 + k] = __float2half_rn(w0);
        g_w16b[nrow * 256 + k] = __float2half_rn(w1);
    }
}

// ---------------- mean gather: padded CSR, int4 idx, no tails ---------------
__global__ void gather_mean(const __half* __restrict__ h, int n) {
    int lane = threadIdx.x & 31;
    int w = (blockIdx.x * blockDim.x + threadIdx.x) >> 5;
    int nw = (gridDim.x * blockDim.x) >> 5;
    const uint2* hb = ((const uint2*)h) + lane;   // row r -> hb[r*32]
    for (int i = w; i < n; i += nw) {
        int beg = g_off[i];
        int n4 = (g_off[i + 1] - beg) >> 2;       // groups of 4 (exact)
        const int4* c4 = (const int4*)(g_csr + beg);
        float4 acc = make_float4(0.f, 0.f, 0.f, 0.f);
        #pragma unroll 2
        for (int j = 0; j < n4; ++j) {
            int4 s4 = __ldg(c4 + j);
            uint2 r0 = __ldg(hb + s4.x * 32);
            uint2 r1 = __ldg(hb + s4.y * 32);
            uint2 r2 = __ldg(hb + s4.z * 32);
            uint2 r3 = __ldg(hb + s4.w * 32);
            __half2 p0 = __hadd2(*(__half2*)&r0.x, *(__half2*)&r1.x);
            __half2 p1 = __hadd2(*(__half2*)&r0.y, *(__half2*)&r1.y);
            __half2 q0 = __hadd2(*(__half2*)&r2.x, *(__half2*)&r3.x);
            __half2 q1 = __hadd2(*(__half2*)&r2.y, *(__half2*)&r3.y);
            float2 fp0 = __half22float2(p0);
            float2 fp1 = __half22float2(p1);
            float2 fq0 = __half22float2(q0);
            float2 fq1 = __half22float2(q1);
            acc.x += fp0.x + fq0.x;
            acc.y += fp0.y + fq0.y;
            acc.z += fp1.x + fq1.x;
            acc.w += fp1.y + fq1.y;
        }
        float inv = 1.0f / fmaxf((float)g_zero[i], 1.0f);   // true degree
        __half2 h01 = __floats2half2_rn(acc.x * inv, acc.y * inv);
        __half2 h23 = __floats2half2_rn(acc.z * inv, acc.w * inv);
        uint2 o;
        o.x = *(unsigned*)&h01;
        o.y = *(unsigned*)&h23;
        *((uint2*)(g_a16 + (size_t)i * D + lane * 4)) = o;
    }
}

// =============================================================================
// fp16 mma.sync GEMM (persistent): out[m][n] = relu(sum_k A[m][k] W[n][k] + b)
// K=256 (A = [agg | feat] fp16). Tile: 256 rows x 128 cols, 16 warps (8m x 2n),
// warp m32 x n64. W resident in smem; next A tile prefetched during epilogue.
// =============================================================================
#define GEMM_GRID 148
#define TM 256
#define SM_B    0        // W fp16 [128][264] (67584 B)
#define SM_A    67584    // A fp16 [256][264] (135168 B)
#define SM_RED  202752   // sS[256], sZ[256], sWl2[128], sWr2[128], sB[128]
#define GEMM_SMEM 206336

__device__ __forceinline__ unsigned su32(const void* p) {
    return (unsigned)__cvta_generic_to_shared(p);
}
__device__ __forceinline__ void cpa16(unsigned dst, const void* src, bool ok) {
    asm volatile("cp.async.cg.shared.global [%0], [%1], 16, %2;"
                 :: "r"(dst), "l"(src), "r"(ok ? 16 : 0));
}
__device__ __forceinline__ void ldm4(unsigned* r, unsigned addr) {
    asm volatile("ldmatrix.sync.aligned.m8n8.x4.shared.b16 {%0,%1,%2,%3}, [%4];"
                 : "=r"(r[0]), "=r"(r[1]), "=r"(r[2]), "=r"(r[3]) : "r"(addr));
}
__device__ __forceinline__ void mma16(float* d, const unsigned* a,
                                      unsigned b0, unsigned b1) {
    asm volatile(
        "mma.sync.aligned.m16n8k16.row.col.f32.f16.f16.f32 "
        "{%0,%1,%2,%3}, {%4,%5,%6,%7}, {%8,%9}, {%0,%1,%2,%3};"
        : "+f"(d[0]), "+f"(d[1]), "+f"(d[2]), "+f"(d[3])
        : "r"(a[0]), "r"(a[1]), "r"(a[2]), "r"(a[3]), "r"(b0), "r"(b1));
}

// A tile loader: 256 rows x 256 fp16 (row = [agg row | feat row]), 528B stride
__device__ __forceinline__ void loadA16(unsigned smb, int tid, int n, int tile,
                                        const __half* agg, const __half* feat) {
    #pragma unroll
    for (int u = tid; u < 8192; u += 512) {
        int r = u >> 5, seg = u & 31;
        int row = tile * TM + r;
        bool ok = row < n;
        const __half* srcb = (seg < 16) ? agg : feat;
        size_t off = (size_t)(ok ? row : 0) * 128 + (seg & 15) * 8;
        cpa16(smb + SM_A + r * 528 + seg * 16, srcb + off, ok);
    }
}

__global__ __launch_bounds__(512, 1) void gemm16(
    const __half* __restrict__ agg, const __half* __restrict__ feat,
    const __half* __restrict__ w16,
    const float* __restrict__ bias,
    __half* __restrict__ outF16,
    const float* __restrict__ Wl2, const float* __restrict__ Wr2,
    int n, int mode)
{
    extern __shared__ char sm[];
    unsigned smb = su32(sm);
    float* sS   = (float*)(sm + SM_RED);   // [256]
    float* sZ   = sS + 256;                // [256]
    float* sWl2 = sZ + 256;                // [128]
    float* sWr2 = sWl2 + 128;              // [128]
    float* sB   = sWr2 + 128;              // [128]

    int tid = threadIdx.x;
    int lane = tid & 31;
    int wid = tid >> 5;
    int mwarp = wid & 7;          // rows [mwarp*32, +32)
    int nwarp = wid >> 3;         // cols [nwarp*64, +64)
    int ntiles = (n + TM - 1) / TM;

    if (tid < 128) {
        sB[tid] = bias[tid];
        if (mode == 1) { sWl2[tid] = Wl2[tid]; sWr2[tid] = Wr2[tid]; }
    }

    // W resident load
    #pragma unroll
    for (int u = tid; u < 4096; u += 512) {
        int nrow = u >> 5, kc = u & 31;
        cpa16(smb + SM_B + nrow * 528 + kc * 16, w16 + nrow * 256 + kc * 8, true);
    }
    int t0 = blockIdx.x;
    if (t0 < ntiles) loadA16(smb, tid, n, t0, agg, feat);
    asm volatile("cp.async.commit_group;");

    // ldmatrix per-thread addresses
    unsigned aAddr = smb + SM_A
        + (mwarp * 32 + (lane & 7) + ((lane >> 3) & 1) * 8) * 528
        + ((lane >> 4) & 1) * 16;
    unsigned bAddr = smb + SM_B
        + (nwarp * 64 + (lane & 7) + ((lane >> 4) & 1) * 8) * 528
        + ((lane >> 3) & 1) * 16;

    int g = lane >> 2, tq = lane & 3;

    for (int t = t0; t < ntiles; t += gridDim.x) {
        if (mode == 1 && tid < 256) { sS[tid] = 0.f; sZ[tid] = 0.f; }

        asm volatile("cp.async.wait_group 0;");
        __syncthreads();

        float acc[2][8][4];
        #pragma unroll
        for (int h = 0; h < 2; ++h)
            #pragma unroll
            for (int i = 0; i < 8; ++i)
                #pragma unroll
                for (int j = 0; j < 4; ++j) acc[h][i][j] = 0.f;

        #pragma unroll
        for (int k = 0; k < 16; ++k) {
            unsigned a0[4], a1[4], b[4];
            ldm4(a0, aAddr + k * 32);
            ldm4(a1, aAddr + 16 * 528 + k * 32);
            #pragma unroll
            for (int p = 0; p < 4; ++p) {
                ldm4(b, bAddr + p * 16 * 528 + k * 32);
                mma16(acc[0][2 * p],     a0, b[0], b[1]);
                mma16(acc[0][2 * p + 1], a0, b[2], b[3]);
                mma16(acc[1][2 * p],     a1, b[0], b[1]);
                mma16(acc[1][2 * p + 1], a1, b[2], b[3]);
            }
        }
        __syncthreads();           // all warps done reading A smem

        int tn = t + gridDim.x;    // prefetch next tile during epilogue
        if (tn < ntiles) loadA16(smb, tid, n, tn, agg, feat);
        asm volatile("cp.async.commit_group;");

        // ---- epilogue ----
        #pragma unroll
        for (int h = 0; h < 2; ++h) {
            int r0 = t * TM + mwarp * 32 + h * 16 + g;
            int r1 = r0 + 8;
            float ps0 = 0.f, pz0 = 0.f, ps1 = 0.f, pz1 = 0.f;
            #pragma unroll
            for (int nt = 0; nt < 8; ++nt) {
                int col = nwarp * 64 + nt * 8 + tq * 2;
                float b0 = sB[col], b1 = sB[col + 1];
                float v0 = fmaxf(acc[h][nt][0] + b0, 0.f);
                float v1 = fmaxf(acc[h][nt][1] + b1, 0.f);
                float v2 = fmaxf(acc[h][nt][2] + b0, 0.f);
                float v3 = fmaxf(acc[h][nt][3] + b1, 0.f);
                if (mode == 0) {
                    if (r0 < n) {
                        __half2 f = __floats2half2_rn(v0, v1);
                        *((unsigned*)(outF16 + (size_t)r0 * D + col)) = *(unsigned*)&f;
                    }
                    if (r1 < n) {
                        __half2 f = __floats2half2_rn(v2, v3);
                        *((unsigned*)(outF16 + (size_t)r1 * D + col)) = *(unsigned*)&f;
                    }
                } else {
                    float wl0 = sWl2[col], wl1 = sWl2[col + 1];
                    float wr0 = sWr2[col], wr1 = sWr2[col + 1];
                    ps0 += v0 * wl0 + v1 * wl1;
                    pz0 += v0 * wr0 + v1 * wr1;
                    ps1 += v2 * wl0 + v3 * wl1;
                    pz1 += v2 * wr0 + v3 * wr1;
                }
            }
            if (mode == 1) {
                #pragma unroll
                for (int m = 1; m <= 2; m <<= 1) {
                    ps0 += __shfl_xor_sync(0xffffffffu, ps0, m);
                    pz0 += __shfl_xor_sync(0xffffffffu, pz0, m);
                    ps1 += __shfl_xor_sync(0xffffffffu, ps1, m);
                    pz1 += __shfl_xor_sync(0xffffffffu, pz1, m);
                }
                if (tq == 0) {
                    int lr = mwarp * 32 + h * 16 + g;
                    atomicAdd(&sS[lr], ps0);
                    atomicAdd(&sZ[lr], pz0);
                    atomicAdd(&sS[lr + 8], ps1);
                    atomicAdd(&sZ[lr + 8], pz1);
                }
            }
        }
        if (mode == 1) {
            __syncthreads();
            if (tid < 256) {
                int row = t * TM + tid;
                if (row < n) { g_s[row] = sS[tid]; g_z[row] = sZ[tid]; }
            }
        }
    }
}

// ---------------- final: mean-gather scalar + bias + sigmoid ----------------
__global__ void final_fused(const float* __restrict__ bl2,
                            float* __restrict__ out, int n) {
    int i = blockIdx.x * blockDim.x + threadIdx.x;
    if (i >= n) return;
    int beg = g_off[i];
    int n4 = (g_off[i + 1] - beg) >> 2;
    const int4* c4 = (const int4*)(g_csr + beg);
    float acc = 0.f;
    for (int j = 0; j < n4; ++j) {
        int4 s4 = __ldg(c4 + j);
        acc += (g_s[s4.x] + g_s[s4.y]) + (g_s[s4.z] + g_s[s4.w]);
    }
    float v = acc / fmaxf((float)g_zero[i], 1.0f) + __ldg(bl2) + g_z[i];
    out[i] = v;
    out[n + i] = 1.0f / (1.0f + expf(-v));
}

// ---------------------------------------------------------------------------
extern "C" void kernel_launch(void* const* d_in, const int* in_sizes, int n_in,
                              void* d_out, int out_size) {
    const float* x   = (const float*)d_in[0];
    const int*   ei  = (const int*)d_in[1];
    const float* Wl0 = (const float*)d_in[2];
    const float* bl0 = (const float*)d_in[3];
    const float* Wr0 = (const float*)d_in[4];
    const float* Wl1 = (const float*)d_in[5];
    const float* bl1 = (const float*)d_in[6];
    const float* Wr1 = (const float*)d_in[7];
    const float* Wl2 = (const float*)d_in[8];
    const float* bl2 = (const float*)d_in[9];
    const float* Wr2 = (const float*)d_in[10];
    float* out = (float*)d_out;

    int n = in_sizes[0] / D;   // 100000
    int E = in_sizes[1] / 2;   // 1600000
    const int* src = ei;
    const int* dst = ei + E;

    void* p_zero;
    cudaGetSymbolAddress(&p_zero, g_zero);
    __half *a16, *f16, *w16a, *w16b;
    cudaGetSymbolAddress((void**)&a16, g_a16);
    cudaGetSymbolAddress((void**)&f16, g_f16);
    cudaGetSymbolAddress((void**)&w16a, g_w16a);
    cudaGetSymbolAddress((void**)&w16b, g_w16b);

    cudaFuncSetAttribute(gemm16, cudaFuncAttributeMaxDynamicSharedMemorySize,
                         GEMM_SMEM);

    int scan_blocks = (n + 1024) / 1024;       // 98 (covers i==n too)

    // zero cnt + scan state; count; padded scan; fused fill+convert+weights
    cudaMemsetAsync(p_zero, 0, (size_t)(NN + 385) * sizeof(int));
    count_kernel<<<1563, 256>>>(dst, E);
    scan_lb<<<scan_blocks, 1024>>>(n);
    build_all<<<6250, 256>>>(src, dst, x, Wl0, Wr0, Wl1, Wr1, n, E);

    // Layer 0
    gather_mean<<<12500, 256>>>(f16, n);
    gemm16<<<GEMM_GRID, 512, GEMM_SMEM>>>(a16, f16, w16a, bl0, f16,
                                          (const float*)0, (const float*)0,
                                          n, 0);

    // Layer 1 (+ fused layer-2 scalarization: s = h2·Wl2, z = h2·Wr2)
    gather_mean<<<12500, 256>>>(f16, n);
    gemm16<<<GEMM_GRID, 512, GEMM_SMEM>>>(a16, f16, w16b, bl1, (__half*)0,
                                          Wl2, Wr2, n, 1);

    // Layer 2 aggregation + output
    final_fused<<<(n + 255) / 256, 256>>>(bl2, out, n);
}